// round 14
// baseline (speedup 1.0000x reference)
#include <cuda_runtime.h>
#include <cstdint>

#define B_  64
#define HW_ 4096
#define C_  128      // N
#define P_  64       // K
#define NCHUNK 32
#define TILE_M 128

// smem tiles (bf16 hi/lo), pitch 72 bf16 (=36 words)
#define PITCH_W 36
#define A_TILE_W (128 * PITCH_W)
#define B_TILE_W (128 * PITCH_W)
#define SMEM_WORDS (2 * A_TILE_W + 2 * B_TILE_W)   // 73728 bytes

// ---------------- scratch ----------------
__device__ float g_zsum[(size_t)B_ * NCHUNK * C_];
__device__ float g_z2[(size_t)B_ * NCHUNK];
__device__ int   g_cnt[B_];          // zero-init; reset after use (deterministic)

// ---------------- helpers ----------------
__device__ __forceinline__ uint32_t bf16x2_rn(float a, float b) {
    uint32_t r;
    asm("cvt.rn.bf16x2.f32 %0, %1, %2;" : "=r"(r) : "f"(b), "f"(a));
    return r;
}
__device__ __forceinline__ void split2(float a, float b, uint32_t& h, uint32_t& l) {
    h = bf16x2_rn(a, b);
    const float fh0 = __uint_as_float(h << 16);
    const float fh1 = __uint_as_float(h & 0xFFFF0000u);
    l = bf16x2_rn(a - fh0, b - fh1);
}
__device__ __forceinline__ void mma_bf16(float* d, const uint32_t* a,
                                         uint32_t b0, uint32_t b1) {
    asm volatile(
        "mma.sync.aligned.m16n8k16.row.col.f32.bf16.bf16.f32 "
        "{%0,%1,%2,%3}, {%4,%5,%6,%7}, {%8,%9}, {%0,%1,%2,%3};"
        : "+f"(d[0]), "+f"(d[1]), "+f"(d[2]), "+f"(d[3])
        : "r"(a[0]), "r"(a[1]), "r"(a[2]), "r"(a[3]), "r"(b0), "r"(b1));
}
#define BAR_MMA() asm volatile("bar.sync 1, 256;" ::: "memory")
#define BAR_Z()   asm volatile("bar.sync 2, 128;" ::: "memory")

// ---------------- single fused kernel ----------------
// 384 threads: warps 0-7 = GEMM, warps 8-11 = z-reduce (+ dist for last CTA/batch)
__global__ __launch_bounds__(384, 1)
void fused_kernel(const float* __restrict__ z, const float* __restrict__ s,
                  const float* __restrict__ kk, float* __restrict__ out,
                  float* __restrict__ dist) {
    extern __shared__ uint32_t sm[];
    uint32_t* sAh = sm;
    uint32_t* sAl = sAh + A_TILE_W;
    uint32_t* sBh = sAl + A_TILE_W;
    uint32_t* sBl = sBh + B_TILE_W;

    __shared__ float4 sredZ[128];
    __shared__ float  szZ[4];
    __shared__ float  zsD[C_];
    __shared__ float  z2sh;
    __shared__ int    sIsLast;

    const int tid  = threadIdx.x;
    const int wid  = tid >> 5;
    const int lane = tid & 31;
    const int bx   = blockIdx.x;
    const size_t m0 = (size_t)bx * TILE_M;
    const int b     = bx >> 5;
    const int chunk = bx & 31;

    if (wid < 8) {
        // ================= GEMM side (threads 0..255) =================
        // ---- stage A (s tile) ----
        #pragma unroll
        for (int i = 0; i < 8; ++i) {
            const int idx = tid + i * 256;
            const int r = idx >> 4, q = idx & 15;
            float4 v = ((const float4*)(s + (m0 + r) * P_))[q];
            uint32_t h0, l0, h1, l1;
            split2(v.x, v.y, h0, l0);
            split2(v.z, v.w, h1, l1);
            uint32_t* ph = sAh + r * PITCH_W + q * 2;
            uint32_t* pl = sAl + r * PITCH_W + q * 2;
            ph[0] = h0; ph[1] = h1;
            pl[0] = l0; pl[1] = l1;
        }
        // ---- stage B (k), kp = lane: conflict-free STS ----
        #pragma unroll
        for (int i = 0; i < 4; ++i) {
            const int idx = tid + i * 256;
            const int kp = idx & 31;
            const int cq = idx >> 5;
            float4 v0 = ((const float4*)(kk + (size_t)(2 * kp)     * C_))[cq];
            float4 v1 = ((const float4*)(kk + (size_t)(2 * kp + 1) * C_))[cq];
            const int n0 = cq * 4;
            uint32_t h, l;
            split2(v0.x, v1.x, h, l);
            sBh[(n0 + 0) * PITCH_W + kp] = h; sBl[(n0 + 0) * PITCH_W + kp] = l;
            split2(v0.y, v1.y, h, l);
            sBh[(n0 + 1) * PITCH_W + kp] = h; sBl[(n0 + 1) * PITCH_W + kp] = l;
            split2(v0.z, v1.z, h, l);
            sBh[(n0 + 2) * PITCH_W + kp] = h; sBl[(n0 + 2) * PITCH_W + kp] = l;
            split2(v0.w, v1.w, h, l);
            sBh[(n0 + 3) * PITCH_W + kp] = h; sBl[(n0 + 3) * PITCH_W + kp] = l;
        }
        BAR_MMA();

        // ---- MMA: warp grid 4(M) x 2(N); warp tile 32x64; 4 k-steps ----
        const int warpM = wid & 3;
        const int warpN = wid >> 2;
        const int lq = lane >> 2;
        const int lr = lane & 3;

        float acc[2][8][4];
        #pragma unroll
        for (int mi = 0; mi < 2; ++mi)
            #pragma unroll
            for (int ni = 0; ni < 8; ++ni)
                #pragma unroll
                for (int j = 0; j < 4; ++j) acc[mi][ni][j] = 0.f;

        #pragma unroll
        for (int ks = 0; ks < 4; ++ks) {
            const int kw = 8 * ks + lr;
            uint32_t ah[2][4], al[2][4];
            #pragma unroll
            for (int mi = 0; mi < 2; ++mi) {
                const int r = warpM * 32 + mi * 16 + lq;
                const uint32_t* bh = sAh + r * PITCH_W + kw;
                const uint32_t* bl = sAl + r * PITCH_W + kw;
                ah[mi][0] = bh[0];
                ah[mi][1] = bh[8 * PITCH_W];
                ah[mi][2] = bh[4];
                ah[mi][3] = bh[8 * PITCH_W + 4];
                al[mi][0] = bl[0];
                al[mi][1] = bl[8 * PITCH_W];
                al[mi][2] = bl[4];
                al[mi][3] = bl[8 * PITCH_W + 4];
            }
            #pragma unroll
            for (int ni = 0; ni < 8; ++ni) {
                const int n = warpN * 64 + ni * 8 + lq;
                const uint32_t* bh = sBh + n * PITCH_W + kw;
                const uint32_t* bl = sBl + n * PITCH_W + kw;
                const uint32_t bh0 = bh[0], bh1 = bh[4];
                const uint32_t bl0 = bl[0], bl1 = bl[4];
                #pragma unroll
                for (int mi = 0; mi < 2; ++mi) {
                    mma_bf16(acc[mi][ni], ah[mi], bh0, bh1);
                    mma_bf16(acc[mi][ni], ah[mi], bl0, bl1);
                    mma_bf16(acc[mi][ni], al[mi], bh0, bh1);
                }
            }
        }

        // ---- epilogue ----
        #pragma unroll
        for (int mi = 0; mi < 2; ++mi) {
            const size_t row = m0 + warpM * 32 + mi * 16 + lq;
            #pragma unroll
            for (int ni = 0; ni < 8; ++ni) {
                const int col = warpN * 64 + ni * 8 + 2 * lr;
                *(float2*)(out + row * C_ + col) =
                    make_float2(acc[mi][ni][0], acc[mi][ni][1]);
                *(float2*)(out + (row + 8) * C_ + col) =
                    make_float2(acc[mi][ni][2], acc[mi][ni][3]);
            }
        }
    } else {
        // ================= z side (threads 256..383, 4 warps) =================
        const int tz = tid - 256;        // 0..127
        const int cq = tz & 31;          // col quad
        const int rg = tz >> 5;          // 0..3
        const float4* base =
            (const float4*)(z + ((size_t)b * HW_ + (size_t)chunk * 128) * C_);

        float4 acc = make_float4(0.f, 0.f, 0.f, 0.f);
        float z2 = 0.f;
        #pragma unroll 8
        for (int j = 0; j < 32; ++j) {
            float4 v = base[(size_t)(rg + 4 * j) * (C_ / 4) + cq];
            acc.x += v.x; acc.y += v.y; acc.z += v.z; acc.w += v.w;
            z2 += v.x * v.x + v.y * v.y + v.z * v.z + v.w * v.w;
        }
        #pragma unroll
        for (int off = 16; off > 0; off >>= 1)
            z2 += __shfl_down_sync(0xffffffffu, z2, off);
        sredZ[tz] = acc;
        if (cq == 0) szZ[rg] = z2;
        BAR_Z();

        if (rg == 0) {
            float4 t = sredZ[cq];
            #pragma unroll
            for (int g = 1; g < 4; ++g) {
                float4 v = sredZ[g * 32 + cq];
                t.x += v.x; t.y += v.y; t.z += v.z; t.w += v.w;
            }
            ((float4*)(g_zsum + ((size_t)b * NCHUNK + chunk) * C_))[cq] = t;
            if (cq == 0)
                g_z2[(size_t)b * NCHUNK + chunk] = szZ[0] + szZ[1] + szZ[2] + szZ[3];
        }

        // completion counter: last CTA of this batch computes dist
        if (tz == 0) {
            __threadfence();
            const int old = atomicAdd(&g_cnt[b], 1);
            sIsLast = (old == NCHUNK - 1);
        }
        BAR_Z();

        if (sIsLast) {
            __threadfence();
            // total zsum per c (fixed order -> deterministic)
            {
                const float* basez = g_zsum + (size_t)b * NCHUNK * C_ + tz;
                float a = 0.f;
                #pragma unroll
                for (int ch = 0; ch < NCHUNK; ++ch) a += basez[(size_t)ch * C_];
                zsD[tz] = a;
            }
            if (tz < 32) {
                float t = g_z2[(size_t)b * NCHUNK + tz];
                #pragma unroll
                for (int off = 16; off > 0; off >>= 1)
                    t += __shfl_down_sync(0xffffffffu, t, off);
                if (tz == 0) z2sh = t;
            }
            BAR_Z();

            const int p   = tz >> 1;
            const int sub = tz & 1;
            const float* kp = kk + (size_t)p * C_ + sub * 64;
            const float* zp = zsD + sub * 64;
            float dot = 0.f, k2 = 0.f;
            #pragma unroll 16
            for (int c = 0; c < 64; ++c) {
                const float kv = kp[c];
                dot += zp[c] * kv;
                k2  += kv * kv;
            }
            dot += __shfl_xor_sync(0xffffffffu, dot, 1);
            k2  += __shfl_xor_sync(0xffffffffu, k2, 1);
            if (sub == 0)
                dist[(size_t)b * P_ + p] = z2sh - 2.f * dot + (float)HW_ * k2;

            if (tz == 0) g_cnt[b] = 0;   // reset for next replay (deterministic)
        }
    }
}

// ---------------- launch ----------------
extern "C" void kernel_launch(void* const* d_in, const int* in_sizes, int n_in,
                              void* d_out, int out_size) {
    const float* z = (const float*)d_in[0];
    const float* s = (const float*)d_in[1];
    const float* k = (const float*)d_in[2];
    float* out  = (float*)d_out;
    float* dist = out + (size_t)in_sizes[0];

    static bool attr_set = false;
    if (!attr_set) {
        cudaFuncSetAttribute(fused_kernel,
                             cudaFuncAttributeMaxDynamicSharedMemorySize,
                             SMEM_WORDS * (int)sizeof(uint32_t));
        attr_set = true;
    }

    fused_kernel<<<(B_ * HW_) / TILE_M, 384, SMEM_WORDS * sizeof(uint32_t)>>>(
        z, s, k, out, dist);
}